// round 3
// baseline (speedup 1.0000x reference)
#include <cuda_runtime.h>

// Scratch for h_src = x_src @ W_nei^T (100000 x 64 f32 = 25.6 MB), 16B-aligned
// (read with LDG.128). __device__ global per the allocation-free rule.
static __device__ __align__(16) float g_h[100000 * 64];

// Edge-index dtype flag: 1 = int64, 0 = int32. Set by detect kernel each call.
static __device__ int g_idx_is64;

// ---------------------------------------------------------------------------
// Detect whether edge indices are int64 or int32 (JAX demotes int64->int32
// when x64 is disabled). Sampling the first E int64 slots is in-bounds under
// BOTH interpretations (int32 buffer = 2E*4 bytes = E int64 slots).
// Int32 data read as int64 has a random high word -> out of [0,n) range.
// ---------------------------------------------------------------------------
__global__ void detect_idx_dtype_kernel(const long long* __restrict__ ei,
                                        int E, int n_src)
{
    if (threadIdx.x != 0 || blockIdx.x != 0) return;
    bool ok64 = true;
    int stride = E > 16 ? E / 16 : 1;
    for (int i = 0; i < 16; i++) {
        long long idx = (long long)i * stride;
        if (idx >= E) break;
        long long v = ei[idx];
        if (v < 0 || v >= n_src) { ok64 = false; break; }
    }
    g_idx_is64 = ok64 ? 1 : 0;
}

// ---------------------------------------------------------------------------
// GEMM: Y[r][c] = sum_k X[r][k] * W[c][k] (+ bias[c])
// N x 64 x 64. Block = 256 threads, 64 rows per block (4 iters x 16 rows).
// ---------------------------------------------------------------------------
__global__ void __launch_bounds__(256) gemm64_kernel(
    const float* __restrict__ X, const float* __restrict__ W,
    const float* __restrict__ bias, float* __restrict__ Y, int N)
{
    // 68-col pad: row stride 272B = 17*16B -> float4 rows stay 16B aligned.
    __shared__ __align__(16) float Ws[64][68];
    __shared__ __align__(16) float Xs[16][68];

    const int tid = threadIdx.x;
    const int c  = tid & 63;
    const int rq = tid >> 6;       // 0..3

    #pragma unroll
    for (int i = 0; i < 16; i++) {
        int idx = i * 256 + tid;           // 0..4095
        Ws[idx >> 6][idx & 63] = W[idx];
    }
    const float bval = bias ? bias[c] : 0.0f;

    const int rowbase = blockIdx.x * 64;

    #pragma unroll 1
    for (int it = 0; it < 4; it++) {
        const int rb = rowbase + it * 16;
        __syncthreads();
        #pragma unroll
        for (int i = 0; i < 4; i++) {
            int idx = i * 256 + tid;       // 0..1023
            int rr = idx >> 6, kk = idx & 63;
            int gr = rb + rr;
            Xs[rr][kk] = (gr < N) ? X[(size_t)gr * 64 + kk] : 0.0f;
        }
        __syncthreads();

        float acc0 = 0.f, acc1 = 0.f, acc2 = 0.f, acc3 = 0.f;
        #pragma unroll
        for (int k4 = 0; k4 < 16; k4++) {
            float4 wv = *(const float4*)&Ws[c][k4 * 4];
            float4 x0 = *(const float4*)&Xs[rq * 4 + 0][k4 * 4];
            float4 x1 = *(const float4*)&Xs[rq * 4 + 1][k4 * 4];
            float4 x2 = *(const float4*)&Xs[rq * 4 + 2][k4 * 4];
            float4 x3 = *(const float4*)&Xs[rq * 4 + 3][k4 * 4];
            acc0 += x0.x * wv.x + x0.y * wv.y + x0.z * wv.z + x0.w * wv.w;
            acc1 += x1.x * wv.x + x1.y * wv.y + x1.z * wv.z + x1.w * wv.w;
            acc2 += x2.x * wv.x + x2.y * wv.y + x2.z * wv.z + x2.w * wv.w;
            acc3 += x3.x * wv.x + x3.y * wv.y + x3.z * wv.z + x3.w * wv.w;
        }

        const int r0 = rb + rq * 4;
        if (r0 + 0 < N) Y[(size_t)(r0 + 0) * 64 + c] = acc0 + bval;
        if (r0 + 1 < N) Y[(size_t)(r0 + 1) * 64 + c] = acc1 + bval;
        if (r0 + 2 < N) Y[(size_t)(r0 + 2) * 64 + c] = acc2 + bval;
        if (r0 + 3 < N) Y[(size_t)(r0 + 3) * 64 + c] = acc3 + bval;
    }
}

// ---------------------------------------------------------------------------
// Edge scatter: out[dst] += g_h[src] * w   (64 floats per edge)
// 16 threads per edge, each owns one float4 lane; vector atomic reduce.
// Branches uniformly on index dtype flag.
// ---------------------------------------------------------------------------
__global__ void __launch_bounds__(256) scatter_kernel(
    const void* __restrict__ ei_raw,    // [2, E]: src row then dst row
    const float* __restrict__ ew,       // [E]
    float* __restrict__ out, int E)
{
    const long long t = (long long)blockIdx.x * blockDim.x + threadIdx.x;
    const long long e = t >> 4;
    const int lane = (int)(t & 15);
    if (e >= E) return;

    long long s, d;
    if (g_idx_is64) {
        const long long* ei = (const long long*)ei_raw;
        s = ei[e];
        d = ei[(long long)E + e];
    } else {
        const int* ei = (const int*)ei_raw;
        s = ei[e];
        d = ei[(long long)E + e];
    }
    const float w = ew[e];

    float4 v = *(const float4*)(g_h + s * 64 + lane * 4);
    v.x *= w; v.y *= w; v.z *= w; v.w *= w;

    float* dst = out + d * 64 + lane * 4;
    asm volatile("red.global.add.v4.f32 [%0], {%1, %2, %3, %4};"
                 :: "l"(dst), "f"(v.x), "f"(v.y), "f"(v.z), "f"(v.w)
                 : "memory");
}

// ---------------------------------------------------------------------------
// Inputs (metadata order):
//   0: x_src f32 [100000*64]   1: x_dst f32 [100000*64]
//   2: edge_index [2*E] (int32 or int64)   3: edge_weight f32 [E]
//   4: W_nei f32 [64*64]   5: W_self f32 [64*64]   6: b_self f32 [64]
// Output: f32 [100000*64]
// ---------------------------------------------------------------------------
extern "C" void kernel_launch(void* const* d_in, const int* in_sizes, int n_in,
                              void* d_out, int out_size)
{
    const float* x_src  = (const float*)d_in[0];
    const float* x_dst  = (const float*)d_in[1];
    const void*  ei     = d_in[2];
    const float* ew     = (const float*)d_in[3];
    const float* W_nei  = (const float*)d_in[4];
    const float* W_self = (const float*)d_in[5];
    const float* b_self = (const float*)d_in[6];
    float*       out    = (float*)d_out;

    const int n_src = in_sizes[0] / 64;
    const int n_dst = in_sizes[1] / 64;
    const int E     = in_sizes[3];

    float* hptr = nullptr;
    cudaGetSymbolAddress((void**)&hptr, g_h);

    // 0) decide edge-index dtype (int32 vs int64)
    detect_idx_dtype_kernel<<<1, 32>>>((const long long*)ei, E, n_src);
    // 1) self term (initializes every output element)
    gemm64_kernel<<<(n_dst + 63) / 64, 256>>>(x_dst, W_self, b_self, out, n_dst);
    // 2) neighbor transform into scratch
    gemm64_kernel<<<(n_src + 63) / 64, 256>>>(x_src, W_nei, nullptr, hptr, n_src);
    // 3) gather-scale-scatter over edges
    {
        long long threads = (long long)E * 16;
        int blocks = (int)((threads + 255) / 256);
        scatter_kernel<<<blocks, 256>>>(ei, ew, out, E);
    }
}

// round 4
// speedup vs baseline: 1.4011x; 1.4011x over previous
#include <cuda_runtime.h>

// Scratch for h_src = x_src @ W_nei^T (100000 x 64 f32 = 25.6 MB), 16B-aligned
// (read with LDG.128). __device__ global per the allocation-free rule.
static __device__ __align__(16) float g_h[100000 * 64];

// Edge-index dtype flag: 1 = int64, 0 = int32. Set by detect kernel each call.
static __device__ int g_idx_is64;

// ---------------------------------------------------------------------------
// Detect whether edge indices are int64 or int32 (JAX demotes int64->int32
// when x64 is disabled). Sampling the first E int64 slots is in-bounds under
// BOTH interpretations. Int32 pairs read as int64 have random high words ->
// out of [0, n_src) with overwhelming probability.
// ---------------------------------------------------------------------------
__global__ void detect_idx_dtype_kernel(const long long* __restrict__ ei,
                                        int E, int n_src)
{
    if (threadIdx.x != 0 || blockIdx.x != 0) return;
    bool ok64 = true;
    int stride = E > 16 ? E / 16 : 1;
    for (int i = 0; i < 16; i++) {
        long long idx = (long long)i * stride;
        if (idx >= E) break;
        long long v = ei[idx];
        if (v < 0 || v >= n_src) { ok64 = false; break; }
    }
    g_idx_is64 = ok64 ? 1 : 0;
}

// ---------------------------------------------------------------------------
// GEMM: Y[r][c] = sum_k X[r][k] * W[c][k] (+ bias[c]),  N x 64 x 64.
// Block = 256 threads = 16x16 thread grid; block tile = 64 rows x 64 cols;
// thread tile = 4x4 (rows r = ty+16i, cols c = tx+16j).
// Shared tiles are XOR-swizzled (chunk = kq ^ (row&15)) -> LDS.128 loads hit
// 16 distinct 16B chunks (2-phase, the 256B floor). FMA-issue bound.
// ---------------------------------------------------------------------------
__global__ void __launch_bounds__(256) gemm64_kernel(
    const float* __restrict__ X, const float* __restrict__ W,
    const float* __restrict__ bias, float* __restrict__ Y, int N)
{
    __shared__ __align__(16) float Xs[64][64];   // [r][swizzled k]
    __shared__ __align__(16) float Ws[64][64];   // [c][swizzled k]

    const int tid = threadIdx.x;
    const int tx = tid & 15;      // col group: c = tx + 16j
    const int ty = tid >> 4;      // row group: r = ty + 16i
    const int rowbase = blockIdx.x * 64;

    // ---- stage W (4096 floats, 4 float4 per thread), swizzled ----
    #pragma unroll
    for (int i = 0; i < 4; i++) {
        int f  = tid + i * 256;           // float4 index 0..1023
        int c  = f >> 4;                  // 0..63
        int kq = f & 15;                  // 16B chunk within row
        float4 v = *(const float4*)(W + c * 64 + kq * 4);
        *(float4*)&Ws[c][(kq ^ (c & 15)) * 4] = v;
    }
    // ---- stage X (bounds-checked), swizzled ----
    #pragma unroll
    for (int i = 0; i < 4; i++) {
        int f  = tid + i * 256;
        int r  = f >> 4;
        int kq = f & 15;
        int gr = rowbase + r;
        float4 v = make_float4(0.f, 0.f, 0.f, 0.f);
        if (gr < N) v = *(const float4*)(X + (size_t)gr * 64 + kq * 4);
        *(float4*)&Xs[r][(kq ^ (r & 15)) * 4] = v;
    }
    __syncthreads();

    float acc[4][4];
    #pragma unroll
    for (int i = 0; i < 4; i++)
        #pragma unroll
        for (int j = 0; j < 4; j++) acc[i][j] = 0.f;

    #pragma unroll
    for (int kq = 0; kq < 16; kq++) {
        const int kx = (kq ^ ty) * 4;   // all 4 rows share (r&15)==ty
        const int kw = (kq ^ tx) * 4;   // all 4 cols share (c&15)==tx
        float4 xv[4], wv[4];
        #pragma unroll
        for (int i = 0; i < 4; i++) xv[i] = *(const float4*)&Xs[ty + 16 * i][kx];
        #pragma unroll
        for (int j = 0; j < 4; j++) wv[j] = *(const float4*)&Ws[tx + 16 * j][kw];
        #pragma unroll
        for (int i = 0; i < 4; i++)
            #pragma unroll
            for (int j = 0; j < 4; j++) {
                acc[i][j] = fmaf(xv[i].x, wv[j].x, acc[i][j]);
                acc[i][j] = fmaf(xv[i].y, wv[j].y, acc[i][j]);
                acc[i][j] = fmaf(xv[i].z, wv[j].z, acc[i][j]);
                acc[i][j] = fmaf(xv[i].w, wv[j].w, acc[i][j]);
            }
    }

    float bval[4];
    #pragma unroll
    for (int j = 0; j < 4; j++) bval[j] = bias ? bias[tx + 16 * j] : 0.f;

    #pragma unroll
    for (int i = 0; i < 4; i++) {
        const int gr = rowbase + ty + 16 * i;
        if (gr < N) {
            float* yrow = Y + (size_t)gr * 64;
            #pragma unroll
            for (int j = 0; j < 4; j++)
                yrow[tx + 16 * j] = acc[i][j] + bval[j];
        }
    }
}

// ---------------------------------------------------------------------------
// Edge scatter: out[dst] += g_h[src] * w  (64 floats per edge).
// 16 lanes per edge-group; each thread owns one float4 slot of 4 consecutive
// edges -> 4 independent L2 gathers in flight (MLP=4), then 4 vector REDs.
// ---------------------------------------------------------------------------
__global__ void __launch_bounds__(256) scatter_kernel(
    const void* __restrict__ ei_raw,    // [2, E]: src row then dst row
    const float* __restrict__ ew,       // [E]
    float* __restrict__ out, int E)
{
    const long long t = (long long)blockIdx.x * blockDim.x + threadIdx.x;
    const int lane = (int)(t & 15);
    const long long e0 = (t >> 4) * 4;
    if (e0 >= E) return;
    const int n = (E - e0 >= 4) ? 4 : (int)(E - e0);

    long long s[4], d[4];
    float w[4];
    if (g_idx_is64) {
        const long long* ei = (const long long*)ei_raw;
        #pragma unroll
        for (int i = 0; i < 4; i++) if (i < n) {
            s[i] = ei[e0 + i];
            d[i] = ei[(long long)E + e0 + i];
        }
    } else {
        const int* ei = (const int*)ei_raw;
        #pragma unroll
        for (int i = 0; i < 4; i++) if (i < n) {
            s[i] = ei[e0 + i];
            d[i] = ei[(long long)E + e0 + i];
        }
    }
    #pragma unroll
    for (int i = 0; i < 4; i++) if (i < n) w[i] = ew[e0 + i];

    float4 v[4];
    #pragma unroll
    for (int i = 0; i < 4; i++) if (i < n)
        v[i] = *(const float4*)(g_h + s[i] * 64 + lane * 4);

    #pragma unroll
    for (int i = 0; i < 4; i++) if (i < n) {
        const float wi = w[i];
        float4 vv = v[i];
        vv.x *= wi; vv.y *= wi; vv.z *= wi; vv.w *= wi;
        float* dst = out + d[i] * 64 + lane * 4;
        asm volatile("red.global.add.v4.f32 [%0], {%1, %2, %3, %4};"
                     :: "l"(dst), "f"(vv.x), "f"(vv.y), "f"(vv.z), "f"(vv.w)
                     : "memory");
    }
}

// ---------------------------------------------------------------------------
// Inputs (metadata order):
//   0: x_src f32 [100000*64]   1: x_dst f32 [100000*64]
//   2: edge_index [2*E] (int32 or int64)   3: edge_weight f32 [E]
//   4: W_nei f32 [64*64]   5: W_self f32 [64*64]   6: b_self f32 [64]
// Output: f32 [100000*64]
// ---------------------------------------------------------------------------
extern "C" void kernel_launch(void* const* d_in, const int* in_sizes, int n_in,
                              void* d_out, int out_size)
{
    const float* x_src  = (const float*)d_in[0];
    const float* x_dst  = (const float*)d_in[1];
    const void*  ei     = d_in[2];
    const float* ew     = (const float*)d_in[3];
    const float* W_nei  = (const float*)d_in[4];
    const float* W_self = (const float*)d_in[5];
    const float* b_self = (const float*)d_in[6];
    float*       out    = (float*)d_out;

    const int n_src = in_sizes[0] / 64;
    const int n_dst = in_sizes[1] / 64;
    const int E     = in_sizes[3];

    float* hptr = nullptr;
    cudaGetSymbolAddress((void**)&hptr, g_h);

    // 0) decide edge-index dtype (int32 vs int64)
    detect_idx_dtype_kernel<<<1, 32>>>((const long long*)ei, E, n_src);
    // 1) self term (initializes every output element)
    gemm64_kernel<<<(n_dst + 63) / 64, 256>>>(x_dst, W_self, b_self, out, n_dst);
    // 2) neighbor transform into scratch
    gemm64_kernel<<<(n_src + 63) / 64, 256>>>(x_src, W_nei, nullptr, hptr, n_src);
    // 3) gather-scale-scatter over edges (4 edges per thread, 16 lanes/edge)
    {
        long long groups  = ((long long)E + 3) / 4;
        long long threads = groups * 16;
        int blocks = (int)((threads + 255) / 256);
        scatter_kernel<<<blocks, 256>>>(ei, ew, out, E);
    }
}